// round 3
// baseline (speedup 1.0000x reference)
#include <cuda_runtime.h>

#define D     256
#define NB    30
#define EG    240
#define BG    2048
#define NHALF 15

// fused fp32x2 FMA (Blackwell packed fp32; ptxas never emits this from C++)
#define FMA2(d, a, b) \
    asm("fma.rn.f32x2 %0, %1, %2, %0;" : "+l"(d) : "l"(a), "l"(b))

// Precomputed folded input-MLP matrices
__device__ float g_Mgeo[5 * D];    // W_geo @ W_lot[0:256]
__device__ float g_Msem[11 * D];   // emb   @ W_lot[256:512]
__device__ float g_bias0[D];       // b_geo @ W_lot[0:256] + b_lot
// K-pair-packed message weights: g_Wp[l][kp*D + c] = (W[2kp][c], W[2kp+1][c])
__device__ unsigned long long g_Wp[3][256 * D];

// ---------------------------------------------------------------------------
__global__ void pre_kernel(const float* __restrict__ Wgeo,
                           const float* __restrict__ bgeo,
                           const float* __restrict__ emb,
                           const float* __restrict__ Wlot,
                           const float* __restrict__ blot)
{
    int c = threadIdx.x;
    int r = blockIdx.x;
    if (r < 5) {
        float a = 0.f;
        for (int j = 0; j < D; j++) a += Wgeo[r * D + j] * Wlot[j * D + c];
        g_Mgeo[r * D + c] = a;
    } else if (r < 16) {
        int s = r - 5;
        float a = 0.f;
        for (int j = 0; j < D; j++) a += emb[s * D + j] * Wlot[(D + j) * D + c];
        g_Msem[s * D + c] = a;
    } else {
        float a = blot[c];
        for (int j = 0; j < D; j++) a += bgeo[j] * Wlot[j * D + c];
        g_bias0[c] = a;
    }
}

__global__ void pack_kernel(const float* __restrict__ W1,
                            const float* __restrict__ W2,
                            const float* __restrict__ W3)
{
    int l  = blockIdx.x >> 8;          // 0..2
    int kp = blockIdx.x & 255;         // 0..255 (over 512 rows / 2)
    int c  = threadIdx.x;
    const float* W = (l == 0) ? W1 : (l == 1) ? W2 : W3;
    unsigned lo = __float_as_uint(W[(2 * kp) * D + c]);
    unsigned hi = __float_as_uint(W[(2 * kp + 1) * D + c]);
    g_Wp[l][kp * D + c] = (unsigned long long)lo | ((unsigned long long)hi << 32);
}

// ---------------------------------------------------------------------------
// One CTA per graph. 512 threads: tid = half*256 + c.
// Thread (c, half) owns output column c for rows [half*15, half*15+15).
// ---------------------------------------------------------------------------
__global__ void __launch_bounds__(512, 2)
graph_kernel(const float* __restrict__ geometry,
             const int*   __restrict__ semantic,
             const int*   __restrict__ e_src,
             const int*   __restrict__ e_dst,
             const float* __restrict__ Wlot,
             const float* __restrict__ bmp1,
             const float* __restrict__ bmp2,
             const float* __restrict__ bmp3,
             const float* __restrict__ Wagg, const float* __restrict__ bagg,
             const float* __restrict__ Wmu,  const float* __restrict__ bmu,
             const float* __restrict__ Wvar, const float* __restrict__ bvar,
             float* __restrict__ out)
{
    extern __shared__ float smem[];
    float* sh_h  = smem;                  // NB*D = 7680
    float* sh_xa = sh_h + NB * D;         // NB*D = 7680
    float* sh_pg = sh_xa + NB * D;        // 2 * 4 * D = 2048
    float* s_geo = sh_pg + 2048;          // NB*5 = 150
    float* s_inv = s_geo + NB * 5;        // NB
    int*   s_sem = (int*)(s_inv + NB);    // NB
    int*   s_cnt = s_sem + NB;            // NB
    int*   s_off = s_cnt + NB;            // NB+1
    int*   s_cur = s_off + NB + 1;        // NB
    int*   s_list = s_cur + NB;           // EG

    const int g    = blockIdx.x;
    const int tid  = threadIdx.x;
    const int c    = tid & (D - 1);
    const int half = tid >> 8;
    const int nb   = half * NHALF;

    // ---- load per-graph data, count degrees ----
    for (int i = tid; i < NB * 5; i += 512) s_geo[i] = geometry[g * NB * 5 + i];
    if (tid < NB) { s_sem[tid] = semantic[g * NB + tid]; s_cnt[tid] = 0; }
    __syncthreads();
    if (tid < EG) {
        int d = e_dst[g * EG + tid] - g * NB;
        atomicAdd(&s_cnt[d], 1);
    }
    __syncthreads();
    // prefix sums (tiny, serial)
    if (tid == 0) {
        int a = 0;
        for (int i = 0; i < NB; i++) { s_off[i] = a; s_cur[i] = a; a += s_cnt[i]; }
        s_off[NB] = a;
    }
    if (tid < NB) s_inv[tid] = s_cnt[tid] ? 1.0f / (float)s_cnt[tid] : 0.0f;
    __syncthreads();
    // CSR fill (built once, reused by all 3 layers)
    if (tid < EG) {
        int s = e_src[g * EG + tid] - g * NB;
        int d = e_dst[g * EG + tid] - g * NB;
        int p = atomicAdd(&s_cur[d], 1);
        s_list[p] = s;
    }

    // ---- h0 = relu(geo@Mgeo + Msem[sem] + W_lot_pos + bias0) ----
    float mg[5];
    #pragma unroll
    for (int i = 0; i < 5; i++) mg[i] = g_Mgeo[i * D + c];
    const float b0 = g_bias0[c];
    float pg = 0.f;
    for (int i = 0; i < NHALF; i++) {
        int n = nb + i;
        float v = b0 + Wlot[(2 * D + n) * D + c] + g_Msem[s_sem[n] * D + c];
        #pragma unroll
        for (int j = 0; j < 5; j++) v = fmaf(s_geo[n * 5 + j], mg[j], v);
        v = fmaxf(v, 0.f);
        sh_h[n * D + c] = v;
        pg = fmaxf(pg, v);
    }
    sh_pg[half * 1024 + 0 * D + c] = pg;
    __syncthreads();   // h0 + CSR visible

    // ---- 3 message-passing layers ----
    const float* bms[3] = { bmp1, bmp2, bmp3 };
    for (int l = 0; l < 3; l++) {
        // gather: xa[n] = mean_{src in N(n)} h[src]
        for (int i = 0; i < NHALF; i++) {
            int n = nb + i;
            float a = 0.f;
            int e1 = s_off[n + 1];
            for (int e = s_off[n]; e < e1; e++)
                a += sh_h[s_list[e] * D + c];
            sh_xa[n * D + c] = a * s_inv[n];
        }
        __syncthreads();

        // GEMM: C = bias + h @ W1 + xa @ W2, K-pair-packed f32x2 accumulation
        const unsigned long long* Wp = g_Wp[l];
        const float bm = bms[l][c];
        unsigned long long acc[NHALF];
        #pragma unroll
        for (int i = 0; i < NHALF; i++)
            acc[i] = (unsigned long long)__float_as_uint(bm);   // lo=bias, hi=0

        const float* Aparts[2] = { sh_h, sh_xa };
        #pragma unroll
        for (int part = 0; part < 2; part++) {
            const float* Ab = Aparts[part] + nb * D;
            const unsigned long long* Wb = Wp + part * 128 * D + c;
            for (int kk = 0; kk < 128; kk += 2) {
                unsigned long long w0 = Wb[kk * D];
                unsigned long long w1 = Wb[(kk + 1) * D];
                const float* hp = Ab + 2 * kk;
                #pragma unroll
                for (int i = 0; i < NHALF; i++) {
                    ulonglong2 hv = *reinterpret_cast<const ulonglong2*>(hp + i * D);
                    FMA2(acc[i], hv.x, w0);
                    FMA2(acc[i], hv.y, w1);
                }
            }
        }
        __syncthreads();   // all reads of sh_h / sh_xa done

        float pgl = 0.f;
        #pragma unroll
        for (int i = 0; i < NHALF; i++) {
            int n = nb + i;
            float lo = __uint_as_float((unsigned)acc[i]);
            float hi = __uint_as_float((unsigned)(acc[i] >> 32));
            float v = s_cnt[n] ? fmaxf(lo + hi, 0.f) : 0.f;   // cnt=0 -> exact 0
            sh_h[n * D + c] = v;
            pgl = fmaxf(pgl, v);
        }
        sh_pg[half * 1024 + (l + 1) * D + c] = pgl;
        __syncthreads();
    }

    // ---- readout ----
    // gvec[1024] = combined per-graph maxes (reuse sh_xa)
    for (int j = tid; j < 4 * D; j += 512)
        sh_xa[j] = fmaxf(sh_pg[j], sh_pg[1024 + j]);
    __syncthreads();

    // latent partial: each half sums 512 of the 1024 terms
    float part = 0.f;
    {
        const int j0 = half * 512;
        for (int j = 0; j < 512; j += 4) {
            float4 gv = *(const float4*)(sh_xa + j0 + j);
            part = fmaf(gv.x, Wagg[(j0 + j + 0) * D + c], part);
            part = fmaf(gv.y, Wagg[(j0 + j + 1) * D + c], part);
            part = fmaf(gv.z, Wagg[(j0 + j + 2) * D + c], part);
            part = fmaf(gv.w, Wagg[(j0 + j + 3) * D + c], part);
        }
    }
    sh_pg[half * D + c] = part;
    __syncthreads();
    if (tid < D)
        sh_h[c] = sh_pg[c] + sh_pg[D + c] + bagg[c];   // latent
    __syncthreads();

    // mu (half 0) / log_var (half 1)
    const float* Wo = half ? Wvar : Wmu;
    float r = half ? bvar[c] : bmu[c];
    for (int j = 0; j < D; j += 4) {
        float4 L = *(const float4*)(sh_h + j);
        r = fmaf(L.x, Wo[(j + 0) * D + c], r);
        r = fmaf(L.y, Wo[(j + 1) * D + c], r);
        r = fmaf(L.z, Wo[(j + 2) * D + c], r);
        r = fmaf(L.w, Wo[(j + 3) * D + c], r);
    }
    out[half * BG * D + g * D + c] = r;
}

// ---------------------------------------------------------------------------
extern "C" void kernel_launch(void* const* d_in, const int* in_sizes, int n_in,
                              void* d_out, int out_size)
{
    const float* geometry = (const float*)d_in[0];
    const int*   semantic = (const int*)d_in[1];
    const int*   eidx     = (const int*)d_in[2];
    const float* Wgeo = (const float*)d_in[4];
    const float* bgeo = (const float*)d_in[5];
    const float* emb  = (const float*)d_in[6];
    const float* Wlot = (const float*)d_in[7];
    const float* blot = (const float*)d_in[8];
    const float* Wmp1 = (const float*)d_in[9];
    const float* bmp1 = (const float*)d_in[10];
    const float* Wmp2 = (const float*)d_in[11];
    const float* bmp2 = (const float*)d_in[12];
    const float* Wmp3 = (const float*)d_in[13];
    const float* bmp3 = (const float*)d_in[14];
    const float* Wagg = (const float*)d_in[15];
    const float* bagg = (const float*)d_in[16];
    const float* Wmu  = (const float*)d_in[17];
    const float* bmu  = (const float*)d_in[18];
    const float* Wvar = (const float*)d_in[19];
    const float* bvar = (const float*)d_in[20];

    const int n_edges = in_sizes[2] / 2;
    const int* e_src = eidx;
    const int* e_dst = eidx + n_edges;

    pre_kernel<<<17, 256>>>(Wgeo, bgeo, emb, Wlot, blot);
    pack_kernel<<<3 * 256, 256>>>(Wmp1, Wmp2, Wmp3);

    size_t smem_bytes = (2 * NB * D + 2048 + NB * 5 + NB) * sizeof(float)
                      + (3 * NB + 1 + EG) * sizeof(int) + 64;
    cudaFuncSetAttribute(graph_kernel, cudaFuncAttributeMaxDynamicSharedMemorySize,
                         (int)smem_bytes);

    graph_kernel<<<BG, 512, smem_bytes>>>(
        geometry, semantic, e_src, e_dst, Wlot,
        bmp1, bmp2, bmp3,
        Wagg, bagg, Wmu, bmu, Wvar, bvar,
        (float*)d_out);
}

// round 5
// speedup vs baseline: 1.0348x; 1.0348x over previous
#include <cuda_runtime.h>

#define D     256
#define NB    30
#define EG    240
#define BG    2048
#define NHALF 15

// fused fp32x2 FMA (Blackwell packed fp32; ptxas never emits this from C++)
#define FMA2(d, a, b) \
    asm("fma.rn.f32x2 %0, %1, %2, %0;" : "+l"(d) : "l"(a), "l"(b))

// Precomputed folded input-MLP matrices
__device__ float g_Mgeo[5 * D];    // W_geo @ W_lot[0:256]
__device__ float g_Msem[11 * D];   // emb   @ W_lot[256:512]
__device__ float g_bias0[D];       // b_geo @ W_lot[0:256] + b_lot
// K-pair-packed message weights: g_Wp[l][kp*D + c] = (W[2kp][c], W[2kp+1][c])
__device__ unsigned long long g_Wp[3][256 * D];

// ---------------------------------------------------------------------------
__global__ void pre_kernel(const float* __restrict__ Wgeo,
                           const float* __restrict__ bgeo,
                           const float* __restrict__ emb,
                           const float* __restrict__ Wlot,
                           const float* __restrict__ blot)
{
    int c = threadIdx.x;
    int r = blockIdx.x;
    if (r < 5) {
        float a = 0.f;
        for (int j = 0; j < D; j++) a += Wgeo[r * D + j] * Wlot[j * D + c];
        g_Mgeo[r * D + c] = a;
    } else if (r < 16) {
        int s = r - 5;
        float a = 0.f;
        for (int j = 0; j < D; j++) a += emb[s * D + j] * Wlot[(D + j) * D + c];
        g_Msem[s * D + c] = a;
    } else {
        float a = blot[c];
        for (int j = 0; j < D; j++) a += bgeo[j] * Wlot[j * D + c];
        g_bias0[c] = a;
    }
}

__global__ void pack_kernel(const float* __restrict__ W1,
                            const float* __restrict__ W2,
                            const float* __restrict__ W3)
{
    int l  = blockIdx.x >> 8;          // 0..2
    int kp = blockIdx.x & 255;         // 0..255 (over 512 rows / 2)
    int c  = threadIdx.x;
    const float* W = (l == 0) ? W1 : (l == 1) ? W2 : W3;
    unsigned lo = __float_as_uint(W[(2 * kp) * D + c]);
    unsigned hi = __float_as_uint(W[(2 * kp + 1) * D + c]);
    g_Wp[l][kp * D + c] = (unsigned long long)lo | ((unsigned long long)hi << 32);
}

// ---------------------------------------------------------------------------
// One CTA per graph. 512 threads: tid = half*256 + c.
// Thread (c, half) owns output column c for rows [half*15, half*15+15).
// launch_bounds(512, 1): 128-reg budget so the 64-bit f32x2 accumulators and
// operand pairs never spill (the R2/R3 regression was spill traffic from the
// 64-reg cap of minBlocksPerMultiprocessor=2).
// ---------------------------------------------------------------------------
__global__ void __launch_bounds__(512, 1)
graph_kernel(const float* __restrict__ geometry,
             const int*   __restrict__ semantic,
             const int*   __restrict__ e_src,
             const int*   __restrict__ e_dst,
             const float* __restrict__ Wlot,
             const float* __restrict__ bmp1,
             const float* __restrict__ bmp2,
             const float* __restrict__ bmp3,
             const float* __restrict__ Wagg, const float* __restrict__ bagg,
             const float* __restrict__ Wmu,  const float* __restrict__ bmu,
             const float* __restrict__ Wvar, const float* __restrict__ bvar,
             float* __restrict__ out)
{
    extern __shared__ float smem[];
    float* sh_h  = smem;                  // NB*D = 7680
    float* sh_xa = sh_h + NB * D;         // NB*D = 7680
    float* sh_pg = sh_xa + NB * D;        // 2 * 4 * D = 2048
    float* s_geo = sh_pg + 2048;          // NB*5 = 150
    float* s_inv = s_geo + NB * 5;        // NB
    int*   s_sem = (int*)(s_inv + NB);    // NB
    int*   s_cnt = s_sem + NB;            // NB
    int*   s_off = s_cnt + NB;            // NB+1
    int*   s_cur = s_off + NB + 1;        // NB
    int*   s_list = s_cur + NB;           // EG

    const int g    = blockIdx.x;
    const int tid  = threadIdx.x;
    const int c    = tid & (D - 1);
    const int half = tid >> 8;
    const int nb   = half * NHALF;

    // ---- load per-graph data, count degrees ----
    for (int i = tid; i < NB * 5; i += 512) s_geo[i] = geometry[g * NB * 5 + i];
    if (tid < NB) { s_sem[tid] = semantic[g * NB + tid]; s_cnt[tid] = 0; }
    __syncthreads();
    if (tid < EG) {
        int d = e_dst[g * EG + tid] - g * NB;
        atomicAdd(&s_cnt[d], 1);
    }
    __syncthreads();
    // prefix sums (tiny, serial)
    if (tid == 0) {
        int a = 0;
        for (int i = 0; i < NB; i++) { s_off[i] = a; s_cur[i] = a; a += s_cnt[i]; }
        s_off[NB] = a;
    }
    if (tid < NB) s_inv[tid] = s_cnt[tid] ? 1.0f / (float)s_cnt[tid] : 0.0f;
    __syncthreads();
    // CSR fill (built once, reused by all 3 layers)
    if (tid < EG) {
        int s = e_src[g * EG + tid] - g * NB;
        int d = e_dst[g * EG + tid] - g * NB;
        int p = atomicAdd(&s_cur[d], 1);
        s_list[p] = s;
    }

    // ---- h0 = relu(geo@Mgeo + Msem[sem] + W_lot_pos + bias0) ----
    float mg[5];
    #pragma unroll
    for (int i = 0; i < 5; i++) mg[i] = g_Mgeo[i * D + c];
    const float b0 = g_bias0[c];
    float pg = 0.f;
    for (int i = 0; i < NHALF; i++) {
        int n = nb + i;
        float v = b0 + Wlot[(2 * D + n) * D + c] + g_Msem[s_sem[n] * D + c];
        #pragma unroll
        for (int j = 0; j < 5; j++) v = fmaf(s_geo[n * 5 + j], mg[j], v);
        v = fmaxf(v, 0.f);
        sh_h[n * D + c] = v;
        pg = fmaxf(pg, v);
    }
    sh_pg[half * 1024 + 0 * D + c] = pg;
    __syncthreads();   // h0 + CSR visible

    // ---- 3 message-passing layers ----
    const float* bms[3] = { bmp1, bmp2, bmp3 };
    for (int l = 0; l < 3; l++) {
        // gather: xa[n] = mean_{src in N(n)} h[src]
        for (int i = 0; i < NHALF; i++) {
            int n = nb + i;
            float a = 0.f;
            int e1 = s_off[n + 1];
            for (int e = s_off[n]; e < e1; e++)
                a += sh_h[s_list[e] * D + c];
            sh_xa[n * D + c] = a * s_inv[n];
        }
        __syncthreads();

        // GEMM: C = bias + h @ W1 + xa @ W2, K-pair-packed f32x2 accumulation
        const unsigned long long* Wp = g_Wp[l];
        const float bm = bms[l][c];
        unsigned long long acc[NHALF];
        #pragma unroll
        for (int i = 0; i < NHALF; i++)
            acc[i] = (unsigned long long)__float_as_uint(bm);   // lo=bias, hi=0

        const float* Aparts[2] = { sh_h, sh_xa };
        #pragma unroll
        for (int part = 0; part < 2; part++) {
            const float* Ab = Aparts[part] + nb * D;
            const unsigned long long* Wb = Wp + part * 128 * D + c;
            for (int kk = 0; kk < 128; kk += 2) {
                unsigned long long w0 = Wb[kk * D];
                unsigned long long w1 = Wb[(kk + 1) * D];
                const float* hp = Ab + 2 * kk;
                #pragma unroll
                for (int i = 0; i < NHALF; i++) {
                    ulonglong2 hv = *reinterpret_cast<const ulonglong2*>(hp + i * D);
                    FMA2(acc[i], hv.x, w0);
                    FMA2(acc[i], hv.y, w1);
                }
            }
        }
        __syncthreads();   // all reads of sh_h / sh_xa done

        float pgl = 0.f;
        #pragma unroll
        for (int i = 0; i < NHALF; i++) {
            int n = nb + i;
            float lo = __uint_as_float((unsigned)acc[i]);
            float hi = __uint_as_float((unsigned)(acc[i] >> 32));
            float v = s_cnt[n] ? fmaxf(lo + hi, 0.f) : 0.f;   // cnt=0 -> exact 0
            sh_h[n * D + c] = v;
            pgl = fmaxf(pgl, v);
        }
        sh_pg[half * 1024 + (l + 1) * D + c] = pgl;
        __syncthreads();
    }

    // ---- readout ----
    // gvec[1024] = combined per-graph maxes (reuse sh_xa)
    for (int j = tid; j < 4 * D; j += 512)
        sh_xa[j] = fmaxf(sh_pg[j], sh_pg[1024 + j]);
    __syncthreads();

    // latent partial: each half sums 512 of the 1024 terms
    float part = 0.f;
    {
        const int j0 = half * 512;
        for (int j = 0; j < 512; j += 4) {
            float4 gv = *(const float4*)(sh_xa + j0 + j);
            part = fmaf(gv.x, Wagg[(j0 + j + 0) * D + c], part);
            part = fmaf(gv.y, Wagg[(j0 + j + 1) * D + c], part);
            part = fmaf(gv.z, Wagg[(j0 + j + 2) * D + c], part);
            part = fmaf(gv.w, Wagg[(j0 + j + 3) * D + c], part);
        }
    }
    sh_pg[half * D + c] = part;
    __syncthreads();
    if (tid < D)
        sh_h[c] = sh_pg[c] + sh_pg[D + c] + bagg[c];   // latent
    __syncthreads();

    // mu (half 0) / log_var (half 1)
    const float* Wo = half ? Wvar : Wmu;
    float r = half ? bvar[c] : bmu[c];
    for (int j = 0; j < D; j += 4) {
        float4 L = *(const float4*)(sh_h + j);
        r = fmaf(L.x, Wo[(j + 0) * D + c], r);
        r = fmaf(L.y, Wo[(j + 1) * D + c], r);
        r = fmaf(L.z, Wo[(j + 2) * D + c], r);
        r = fmaf(L.w, Wo[(j + 3) * D + c], r);
    }
    out[half * BG * D + g * D + c] = r;
}

// ---------------------------------------------------------------------------
extern "C" void kernel_launch(void* const* d_in, const int* in_sizes, int n_in,
                              void* d_out, int out_size)
{
    const float* geometry = (const float*)d_in[0];
    const int*   semantic = (const int*)d_in[1];
    const int*   eidx     = (const int*)d_in[2];
    const float* Wgeo = (const float*)d_in[4];
    const float* bgeo = (const float*)d_in[5];
    const float* emb  = (const float*)d_in[6];
    const float* Wlot = (const float*)d_in[7];
    const float* blot = (const float*)d_in[8];
    const float* Wmp1 = (const float*)d_in[9];
    const float* bmp1 = (const float*)d_in[10];
    const float* Wmp2 = (const float*)d_in[11];
    const float* bmp2 = (const float*)d_in[12];
    const float* Wmp3 = (const float*)d_in[13];
    const float* bmp3 = (const float*)d_in[14];
    const float* Wagg = (const float*)d_in[15];
    const float* bagg = (const float*)d_in[16];
    const float* Wmu  = (const float*)d_in[17];
    const float* bmu  = (const float*)d_in[18];
    const float* Wvar = (const float*)d_in[19];
    const float* bvar = (const float*)d_in[20];

    const int n_edges = in_sizes[2] / 2;
    const int* e_src = eidx;
    const int* e_dst = eidx + n_edges;

    pre_kernel<<<17, 256>>>(Wgeo, bgeo, emb, Wlot, blot);
    pack_kernel<<<3 * 256, 256>>>(Wmp1, Wmp2, Wmp3);

    size_t smem_bytes = (2 * NB * D + 2048 + NB * 5 + NB) * sizeof(float)
                      + (3 * NB + 1 + EG) * sizeof(int) + 64;
    cudaFuncSetAttribute(graph_kernel, cudaFuncAttributeMaxDynamicSharedMemorySize,
                         (int)smem_bytes);

    graph_kernel<<<BG, 512, smem_bytes>>>(
        geometry, semantic, e_src, e_dst, Wlot,
        bmp1, bmp2, bmp3,
        Wagg, bagg, Wmu, bmu, Wvar, bvar,
        (float*)d_out);
}

// round 6
// speedup vs baseline: 1.4757x; 1.4261x over previous
#include <cuda_runtime.h>

#define D     256
#define NB    30
#define EG    240
#define BG    2048
#define NHALF 15

// Precomputed folded input-MLP matrices
__device__ float g_Mgeo[5 * D];    // W_geo @ W_lot[0:256]
__device__ float g_Msem[11 * D];   // emb   @ W_lot[256:512]
__device__ float g_bias0[D];       // b_geo @ W_lot[0:256] + b_lot

// ---------------------------------------------------------------------------
__global__ void pre_kernel(const float* __restrict__ Wgeo,
                           const float* __restrict__ bgeo,
                           const float* __restrict__ emb,
                           const float* __restrict__ Wlot,
                           const float* __restrict__ blot)
{
    int c = threadIdx.x;
    int r = blockIdx.x;
    if (r < 5) {
        float a = 0.f;
        for (int j = 0; j < D; j++) a += Wgeo[r * D + j] * Wlot[j * D + c];
        g_Mgeo[r * D + c] = a;
    } else if (r < 16) {
        int s = r - 5;
        float a = 0.f;
        for (int j = 0; j < D; j++) a += emb[s * D + j] * Wlot[(D + j) * D + c];
        g_Msem[s * D + c] = a;
    } else {
        float a = blot[c];
        for (int j = 0; j < D; j++) a += bgeo[j] * Wlot[j * D + c];
        g_bias0[c] = a;
    }
}

// ---------------------------------------------------------------------------
// One CTA per graph. 256 threads: tid = half*128 + cp.
// Thread (half, cp) owns columns {2cp, 2cp+1} for rows [half*15, half*15+15).
// Column-pair blocking: each LDS.128 of h feeds 8 FMAs (2 cols x 4 k) instead
// of 4, halving the L1 wavefront traffic that bound round 1.
// ---------------------------------------------------------------------------
__global__ void __launch_bounds__(256, 2)
graph_kernel(const float* __restrict__ geometry,
             const int*   __restrict__ semantic,
             const int*   __restrict__ e_src,
             const int*   __restrict__ e_dst,
             const float* __restrict__ Wlot,
             const float* __restrict__ Wmp1, const float* __restrict__ bmp1,
             const float* __restrict__ Wmp2, const float* __restrict__ bmp2,
             const float* __restrict__ Wmp3, const float* __restrict__ bmp3,
             const float* __restrict__ Wagg, const float* __restrict__ bagg,
             const float* __restrict__ Wmu,  const float* __restrict__ bmu,
             const float* __restrict__ Wvar, const float* __restrict__ bvar,
             float* __restrict__ out)
{
    extern __shared__ float smem[];
    float* sh_h  = smem;                  // NB*D = 7680
    float* sh_xa = sh_h + NB * D;         // NB*D = 7680
    float* sh_pg = sh_xa + NB * D;        // 2 * 4 * D = 2048
    float* s_geo = sh_pg + 2048;          // NB*5
    float* s_inv = s_geo + NB * 5;        // NB
    int*   s_sem = (int*)(s_inv + NB);    // NB
    int*   s_cnt = s_sem + NB;            // NB
    int*   s_off = s_cnt + NB;            // NB+1
    int*   s_cur = s_off + NB + 1;        // NB
    int*   s_list = s_cur + NB;           // EG

    const int g    = blockIdx.x;
    const int tid  = threadIdx.x;
    const int cp   = tid & 127;
    const int half = tid >> 7;
    const int c0   = 2 * cp;
    const int nb   = half * NHALF;

    // ---- load per-graph data, count degrees ----
    for (int i = tid; i < NB * 5; i += 256) s_geo[i] = geometry[g * NB * 5 + i];
    if (tid < NB) { s_sem[tid] = semantic[g * NB + tid]; s_cnt[tid] = 0; }
    __syncthreads();
    if (tid < EG) {
        int d = e_dst[g * EG + tid] - g * NB;
        atomicAdd(&s_cnt[d], 1);
    }
    __syncthreads();
    if (tid == 0) {
        int a = 0;
        for (int i = 0; i < NB; i++) { s_off[i] = a; s_cur[i] = a; a += s_cnt[i]; }
        s_off[NB] = a;
    }
    if (tid < NB) s_inv[tid] = s_cnt[tid] ? 1.0f / (float)s_cnt[tid] : 0.0f;
    __syncthreads();
    if (tid < EG) {
        int s = e_src[g * EG + tid] - g * NB;
        int d = e_dst[g * EG + tid] - g * NB;
        int p = atomicAdd(&s_cur[d], 1);
        s_list[p] = s;
    }

    // ---- h0 = relu(geo@Mgeo + Msem[sem] + W_lot_pos + bias0), 2 cols ----
    float2 mg[5];
    #pragma unroll
    for (int j = 0; j < 5; j++) mg[j] = *(const float2*)(g_Mgeo + j * D + c0);
    const float2 b0 = *(const float2*)(g_bias0 + c0);
    float2 pg = make_float2(0.f, 0.f);
    for (int i = 0; i < NHALF; i++) {
        int n = nb + i;
        float2 wl = *(const float2*)(Wlot + (2 * D + n) * D + c0);
        float2 ms = *(const float2*)(g_Msem + s_sem[n] * D + c0);
        float2 v = make_float2(b0.x + wl.x + ms.x, b0.y + wl.y + ms.y);
        #pragma unroll
        for (int j = 0; j < 5; j++) {
            float ge = s_geo[n * 5 + j];
            v.x = fmaf(ge, mg[j].x, v.x);
            v.y = fmaf(ge, mg[j].y, v.y);
        }
        v.x = fmaxf(v.x, 0.f); v.y = fmaxf(v.y, 0.f);
        *(float2*)(sh_h + n * D + c0) = v;
        pg.x = fmaxf(pg.x, v.x); pg.y = fmaxf(pg.y, v.y);
    }
    *(float2*)(sh_pg + half * 1024 + 0 * D + c0) = pg;
    __syncthreads();   // h0 + CSR visible

    // ---- 3 message-passing layers ----
    const float* Wms[3] = { Wmp1, Wmp2, Wmp3 };
    const float* bms[3] = { bmp1, bmp2, bmp3 };

    for (int l = 0; l < 3; l++) {
        // gather: xa[n] = mean_{src in N(n)} h[src], 2 cols at once
        for (int i = 0; i < NHALF; i++) {
            int n = nb + i;
            float2 a = make_float2(0.f, 0.f);
            int e1 = s_off[n + 1];
            for (int e = s_off[n]; e < e1; e++) {
                float2 hv = *(const float2*)(sh_h + s_list[e] * D + c0);
                a.x += hv.x; a.y += hv.y;
            }
            float inv = s_inv[n];
            a.x *= inv; a.y *= inv;
            *(float2*)(sh_xa + n * D + c0) = a;
        }
        __syncthreads();

        // GEMM: C[n][c0..c0+1] = b + h[n]@W1 + xa[n]@W2
        const float* W  = Wms[l];
        const float2 bm = *(const float2*)(bms[l] + c0);
        float2 acc[NHALF];
        #pragma unroll
        for (int i = 0; i < NHALF; i++) acc[i] = bm;

        #pragma unroll
        for (int part = 0; part < 2; part++) {
            const float* A  = (part ? sh_xa : sh_h) + nb * D;
            const float* Wb = W + part * D * D;
            for (int k4 = 0; k4 < D; k4 += 4) {
                float2 w0 = *(const float2*)(Wb + (k4 + 0) * D + c0);
                float2 w1 = *(const float2*)(Wb + (k4 + 1) * D + c0);
                float2 w2 = *(const float2*)(Wb + (k4 + 2) * D + c0);
                float2 w3 = *(const float2*)(Wb + (k4 + 3) * D + c0);
                #pragma unroll
                for (int i = 0; i < NHALF; i++) {
                    float4 hv = *(const float4*)(A + i * D + k4);
                    float2 a = acc[i];
                    a.x = fmaf(hv.x, w0.x, a.x);  a.y = fmaf(hv.x, w0.y, a.y);
                    a.x = fmaf(hv.y, w1.x, a.x);  a.y = fmaf(hv.y, w1.y, a.y);
                    a.x = fmaf(hv.z, w2.x, a.x);  a.y = fmaf(hv.z, w2.y, a.y);
                    a.x = fmaf(hv.w, w3.x, a.x);  a.y = fmaf(hv.w, w3.y, a.y);
                    acc[i] = a;
                }
            }
        }
        __syncthreads();   // all reads of sh_h / sh_xa done

        float2 pgl = make_float2(0.f, 0.f);
        #pragma unroll
        for (int i = 0; i < NHALF; i++) {
            int n = nb + i;
            float2 v;
            if (s_cnt[n]) {
                v.x = fmaxf(acc[i].x, 0.f);
                v.y = fmaxf(acc[i].y, 0.f);
            } else {
                v = make_float2(0.f, 0.f);   // cnt=0 -> exact 0
            }
            *(float2*)(sh_h + n * D + c0) = v;
            pgl.x = fmaxf(pgl.x, v.x); pgl.y = fmaxf(pgl.y, v.y);
        }
        *(float2*)(sh_pg + half * 1024 + (l + 1) * D + c0) = pgl;
        __syncthreads();
    }

    // ---- readout ----
    // gvec[1024] = combined per-graph maxes over both halves (reuse sh_xa)
    for (int j = tid; j < 4 * D; j += 256)
        sh_xa[j] = fmaxf(sh_pg[j], sh_pg[1024 + j]);
    __syncthreads();

    // latent partial: each half sums 512 of the 1024 terms, 2 cols
    float2 part = make_float2(0.f, 0.f);
    {
        const int j0 = half * 512;
        for (int j = j0; j < j0 + 512; j += 4) {
            float4 gv = *(const float4*)(sh_xa + j);
            float2 a0 = *(const float2*)(Wagg + (j + 0) * D + c0);
            float2 a1 = *(const float2*)(Wagg + (j + 1) * D + c0);
            float2 a2 = *(const float2*)(Wagg + (j + 2) * D + c0);
            float2 a3 = *(const float2*)(Wagg + (j + 3) * D + c0);
            part.x = fmaf(gv.x, a0.x, part.x);  part.y = fmaf(gv.x, a0.y, part.y);
            part.x = fmaf(gv.y, a1.x, part.x);  part.y = fmaf(gv.y, a1.y, part.y);
            part.x = fmaf(gv.z, a2.x, part.x);  part.y = fmaf(gv.z, a2.y, part.y);
            part.x = fmaf(gv.w, a3.x, part.x);  part.y = fmaf(gv.w, a3.y, part.y);
        }
    }
    *(float2*)(sh_pg + half * D + c0) = part;
    __syncthreads();
    if (tid < 128) {
        float2 p0 = *(const float2*)(sh_pg + c0);
        float2 p1 = *(const float2*)(sh_pg + D + c0);
        float2 bg = *(const float2*)(bagg + c0);
        float2 lat = make_float2(p0.x + p1.x + bg.x, p0.y + p1.y + bg.y);
        *(float2*)(sh_h + c0) = lat;
    }
    __syncthreads();

    // mu (half 0) / log_var (half 1), 2 cols per thread
    const float* Wo = half ? Wvar : Wmu;
    const float* bo = half ? bvar : bmu;
    float2 r = *(const float2*)(bo + c0);
    for (int j = 0; j < D; j += 4) {
        float4 L = *(const float4*)(sh_h + j);
        float2 o0 = *(const float2*)(Wo + (j + 0) * D + c0);
        float2 o1 = *(const float2*)(Wo + (j + 1) * D + c0);
        float2 o2 = *(const float2*)(Wo + (j + 2) * D + c0);
        float2 o3 = *(const float2*)(Wo + (j + 3) * D + c0);
        r.x = fmaf(L.x, o0.x, r.x);  r.y = fmaf(L.x, o0.y, r.y);
        r.x = fmaf(L.y, o1.x, r.x);  r.y = fmaf(L.y, o1.y, r.y);
        r.x = fmaf(L.z, o2.x, r.x);  r.y = fmaf(L.z, o2.y, r.y);
        r.x = fmaf(L.w, o3.x, r.x);  r.y = fmaf(L.w, o3.y, r.y);
    }
    *(float2*)(out + half * BG * D + g * D + c0) = r;
}

// ---------------------------------------------------------------------------
extern "C" void kernel_launch(void* const* d_in, const int* in_sizes, int n_in,
                              void* d_out, int out_size)
{
    const float* geometry = (const float*)d_in[0];
    const int*   semantic = (const int*)d_in[1];
    const int*   eidx     = (const int*)d_in[2];
    const float* Wgeo = (const float*)d_in[4];
    const float* bgeo = (const float*)d_in[5];
    const float* emb  = (const float*)d_in[6];
    const float* Wlot = (const float*)d_in[7];
    const float* blot = (const float*)d_in[8];
    const float* Wmp1 = (const float*)d_in[9];
    const float* bmp1 = (const float*)d_in[10];
    const float* Wmp2 = (const float*)d_in[11];
    const float* bmp2 = (const float*)d_in[12];
    const float* Wmp3 = (const float*)d_in[13];
    const float* bmp3 = (const float*)d_in[14];
    const float* Wagg = (const float*)d_in[15];
    const float* bagg = (const float*)d_in[16];
    const float* Wmu  = (const float*)d_in[17];
    const float* bmu  = (const float*)d_in[18];
    const float* Wvar = (const float*)d_in[19];
    const float* bvar = (const float*)d_in[20];

    const int n_edges = in_sizes[2] / 2;
    const int* e_src = eidx;
    const int* e_dst = eidx + n_edges;

    pre_kernel<<<17, 256>>>(Wgeo, bgeo, emb, Wlot, blot);

    size_t smem_bytes = (2 * NB * D + 2048 + NB * 5 + NB) * sizeof(float)
                      + (3 * NB + 1 + EG) * sizeof(int) + 64;
    cudaFuncSetAttribute(graph_kernel, cudaFuncAttributeMaxDynamicSharedMemorySize,
                         (int)smem_bytes);

    graph_kernel<<<BG, 256, smem_bytes>>>(
        geometry, semantic, e_src, e_dst, Wlot,
        Wmp1, bmp1, Wmp2, bmp2, Wmp3, bmp3,
        Wagg, bagg, Wmu, bmu, Wvar, bvar,
        (float*)d_out);
}